// round 1
// baseline (speedup 1.0000x reference)
#include <cuda_runtime.h>
#include <math.h>

#define NMAX 4096
#define NPIX (96*96)

// ---- scratch (device globals; no allocation allowed) ----
__device__ float g_u0[NMAX], g_u1[NMAX], g_hA[NMAX], g_hB[NMAX], g_hC[NMAX];
__device__ float g_al[NMAX], g_cr[NMAX], g_cg[NMAX], g_cb[NMAX], g_rc2[NMAX], g_depth[NMAX];
// sorted versions
__device__ float o_u0[NMAX], o_u1[NMAX], o_hA[NMAX], o_hB[NMAX], o_hC[NMAX];
__device__ float o_al[NMAX], o_cr[NMAX], o_cg[NMAX], o_cb[NMAX], o_rc2[NMAX];

__constant__ float kC0 = 0.28209479177387814f;
__constant__ float kC1 = 0.4886025119029199f;

// ---------------- Kernel A: per-gaussian preprocess ----------------
__global__ void prep_kernel(const float* __restrict__ pws,
                            const float* __restrict__ lows,
                            const float* __restrict__ highs,
                            const float* __restrict__ araw,
                            const float* __restrict__ sraw,
                            const float* __restrict__ qraw,
                            const float* __restrict__ Rcw,
                            const float* __restrict__ tcw,
                            const float* __restrict__ cam,
                            float* __restrict__ out_areas,
                            int n)
{
    int i = blockIdx.x * blockDim.x + threadIdx.x;
    if (i >= n) return;

    float fx = cam[0], fy = cam[1], cx = cam[2], cy = cam[3];
    float R00=Rcw[0],R01=Rcw[1],R02=Rcw[2];
    float R10=Rcw[3],R11=Rcw[4],R12=Rcw[5];
    float R20=Rcw[6],R21=Rcw[7],R22=Rcw[8];
    float t0=tcw[0],t1=tcw[1],t2=tcw[2];

    float pwx=pws[3*i], pwy=pws[3*i+1], pwz=pws[3*i+2];
    float pcx = R00*pwx + R01*pwy + R02*pwz + t0;
    float pcy = R10*pwx + R11*pwy + R12*pwz + t1;
    float pcz = R20*pwx + R21*pwy + R22*pwz + t2;
    float depth = pcz;
    float zs = (depth > 1e-6f) ? depth : 1e-6f;
    float inv_z = 1.0f / zs;
    float u0 = fx * pcx * inv_z + cx;
    float u1 = fy * pcy * inv_z + cy;

    // scales / quaternion
    float s0 = expf(sraw[3*i]), s1 = expf(sraw[3*i+1]), s2 = expf(sraw[3*i+2]);
    float qw=qraw[4*i], qx=qraw[4*i+1], qy=qraw[4*i+2], qz=qraw[4*i+3];
    float qn = rsqrtf(qw*qw + qx*qx + qy*qy + qz*qz);
    qw*=qn; qx*=qn; qy*=qn; qz*=qn;
    float r00 = 1.f-2.f*(qy*qy+qz*qz), r01 = 2.f*(qx*qy-qw*qz), r02 = 2.f*(qx*qz+qw*qy);
    float r10 = 2.f*(qx*qy+qw*qz), r11 = 1.f-2.f*(qx*qx+qz*qz), r12 = 2.f*(qy*qz-qw*qx);
    float r20 = 2.f*(qx*qz-qw*qy), r21 = 2.f*(qy*qz+qw*qx), r22 = 1.f-2.f*(qx*qx+qy*qy);

    float v0=s0*s0, v1=s1*s1, v2=s2*s2;
    float c00 = v0*r00*r00 + v1*r01*r01 + v2*r02*r02;
    float c01 = v0*r00*r10 + v1*r01*r11 + v2*r02*r12;
    float c02 = v0*r00*r20 + v1*r01*r21 + v2*r02*r22;
    float c11 = v0*r10*r10 + v1*r11*r11 + v2*r12*r12;
    float c12 = v0*r10*r20 + v1*r11*r21 + v2*r12*r22;
    float c22 = v0*r20*r20 + v1*r21*r21 + v2*r22*r22;

    float limx = 1.3f * (96.0f / (2.0f*fx));
    float limy = 1.3f * (96.0f / (2.0f*fy));
    float txc = fminf(fmaxf(pcx*inv_z, -limx), limx) * zs;
    float tyc = fminf(fmaxf(pcy*inv_z, -limy), limy) * zs;
    float J00 = fx*inv_z, J02 = -fx*txc*inv_z*inv_z;
    float J11 = fy*inv_z, J12 = -fy*tyc*inv_z*inv_z;

    // T = J @ Rcw (2x3)
    float T00 = J00*R00 + J02*R20, T01 = J00*R01 + J02*R21, T02 = J00*R02 + J02*R22;
    float T10 = J11*R10 + J12*R20, T11 = J11*R11 + J12*R21, T12 = J11*R12 + J12*R22;

    // tmp = T @ cov3d
    float m00 = T00*c00 + T01*c01 + T02*c02;
    float m01 = T00*c01 + T01*c11 + T02*c12;
    float m02 = T00*c02 + T01*c12 + T02*c22;
    float m10 = T10*c00 + T11*c01 + T12*c02;
    float m11 = T10*c01 + T11*c11 + T12*c12;
    float m12 = T10*c02 + T11*c12 + T12*c22;

    float A  = m00*T00 + m01*T01 + m02*T02 + 0.3f;
    float Bb = m00*T10 + m01*T11 + m02*T12;
    float Cc = m10*T10 + m11*T11 + m12*T12 + 0.3f;

    float det  = A*Cc - Bb*Bb;
    float idet = 1.0f / det;
    // power = hA*dx*dx + hC*dy*dy + hB*dx*dy   (reference: -0.5*(c/det*dx^2 + a/det*dy^2) + b/det*dx*dy)
    float hA = -0.5f * Cc * idet;
    float hC = -0.5f * A  * idet;
    float hB =  Bb * idet;

    float mid = 0.5f * (A + Cc);
    float lam = mid + sqrtf(fmaxf(mid*mid - det, 0.1f));
    float radius = ceilf(3.0f * sqrtf(lam));
    out_areas[2*i]   = radius;
    out_areas[2*i+1] = radius;

    float alpha = 1.0f / (1.0f + expf(-araw[i]));
    if (!(depth > 0.2f)) alpha = 0.0f;   // fold 'valid' into alpha

    // conservative cull radius^2: keep iff dist^2 <= lam * 2*ln(255*alpha)
    float rc2;
    if (alpha * 255.0f <= 1.0f) {
        rc2 = -1.0f;  // never contributes (ap < 1/255 everywhere)
    } else {
        float theta = 2.0f * logf(255.0f * alpha);
        rc2 = lam * theta * 1.002f + 1e-2f;   // small safety margin (bound already conservative)
    }

    // SH color: dir = pw - twc,  twc = -(Rcw^T @ tcw)  => dir = pw + Rcw^T tcw
    float wx = R00*t0 + R10*t1 + R20*t2;
    float wy = R01*t0 + R11*t1 + R21*t2;
    float wz = R02*t0 + R12*t1 + R22*t2;
    float dx0 = pwx + wx, dy0 = pwy + wy, dz0 = pwz + wz;
    float dn = rsqrtf(dx0*dx0 + dy0*dy0 + dz0*dz0);
    float x = dx0*dn, y = dy0*dn, z = dz0*dn;
    float xx=x*x, yy=y*y, zz=z*z, xy=x*y, yz=y*z, xz=x*z;

    float b1 = -kC1*y, b2 = kC1*z, b3 = -kC1*x;
    float b4 =  1.0925484305920792f  * xy;
    float b5 = -1.0925484305920792f  * yz;
    float b6 =  0.31539156525252005f * (2.f*zz - xx - yy);
    float b7 = -1.0925484305920792f  * xz;
    float b8 =  0.5462742152960396f  * (xx - yy);
    float b9  = -0.5900435899266435f * y * (3.f*xx - yy);
    float b10 =  2.890611442640554f  * xy * z;
    float b11 = -0.4570457994644658f * y * (4.f*zz - xx - yy);
    float b12 =  0.3731763325901154f * z * (2.f*zz - 3.f*xx - 3.f*yy);
    float b13 = -0.4570457994644658f * x * (4.f*zz - xx - yy);
    float b14 =  1.445305721320277f  * z * (xx - yy);
    float b15 = -0.5900435899266435f * x * (xx - 3.f*yy);

    const float* hs = highs + 45*i;
    float col[3];
    #pragma unroll
    for (int ch = 0; ch < 3; ch++) {
        float c = kC0 * lows[3*i + ch];
        c += b1  * hs[0*3+ch]  + b2  * hs[1*3+ch]  + b3  * hs[2*3+ch];
        c += b4  * hs[3*3+ch]  + b5  * hs[4*3+ch]  + b6  * hs[5*3+ch];
        c += b7  * hs[6*3+ch]  + b8  * hs[7*3+ch];
        c += b9  * hs[8*3+ch]  + b10 * hs[9*3+ch]  + b11 * hs[10*3+ch];
        c += b12 * hs[11*3+ch] + b13 * hs[12*3+ch] + b14 * hs[13*3+ch];
        c += b15 * hs[14*3+ch];
        col[ch] = fmaxf(c + 0.5f, 0.0f);
    }

    g_u0[i]=u0; g_u1[i]=u1; g_hA[i]=hA; g_hB[i]=hB; g_hC[i]=hC;
    g_al[i]=alpha; g_cr[i]=col[0]; g_cg[i]=col[1]; g_cb[i]=col[2];
    g_rc2[i]=rc2; g_depth[i]=depth;
}

// ---------------- Kernel B: bitonic sort by depth + gather ----------------
__global__ void sort_kernel(int n)
{
    __shared__ float key[NMAX];
    __shared__ int   val[NMAX];
    int tid = threadIdx.x;
    for (int i = tid; i < NMAX; i += blockDim.x) {
        key[i] = (i < n) ? g_depth[i] : 3.4e38f;
        val[i] = i;
    }
    __syncthreads();

    for (int size = 2; size <= NMAX; size <<= 1) {
        for (int stride = size >> 1; stride > 0; stride >>= 1) {
            for (int t = tid; t < NMAX/2; t += blockDim.x) {
                int low = t & (stride - 1);
                int ii  = (t << 1) - low;
                int jj  = ii + stride;
                bool asc = ((ii & size) == 0);
                float k0 = key[ii], k1 = key[jj];
                if ((k0 > k1) == asc) {
                    key[ii] = k1; key[jj] = k0;
                    int v = val[ii]; val[ii] = val[jj]; val[jj] = v;
                }
            }
            __syncthreads();
        }
    }

    for (int i = tid; i < n; i += blockDim.x) {
        int j = val[i];
        o_u0[i]=g_u0[j]; o_u1[i]=g_u1[j];
        o_hA[i]=g_hA[j]; o_hB[i]=g_hB[j]; o_hC[i]=g_hC[j];
        o_al[i]=g_al[j]; o_cr[i]=g_cr[j]; o_cg[i]=g_cg[j]; o_cb[i]=g_cb[j];
        o_rc2[i]=g_rc2[j];
    }
}

// ---------------- Kernel C: tiled alpha blending ----------------
// grid (12,12) tiles of 8x8 pixels; block 64 threads; chunked culling + compaction.
__global__ void blend_kernel(float* __restrict__ out, int n)
{
    const int txr = threadIdx.x, tyr = threadIdx.y;
    const int tid = tyr * 8 + txr;
    const int warp = tid >> 5, lane = tid & 31;
    const float fpx = (float)(blockIdx.x * 8 + txr);
    const float fpy = (float)(blockIdx.y * 8 + tyr);
    const float x0 = (float)(blockIdx.x * 8), x1 = x0 + 7.0f;
    const float y0 = (float)(blockIdx.y * 8), y1 = y0 + 7.0f;

    float tau = 1.0f, acc0 = 0.f, acc1 = 0.f, acc2 = 0.f;

    __shared__ float su0[64], su1[64], sA[64], sB[64], sC[64];
    __shared__ float sal[64], scr[64], scg[64], scb[64];
    __shared__ int wc[2];

    for (int base = 0; base < n; base += 64) {
        int gi = base + tid;
        bool keep = false;
        float u0 = 0.f, u1 = 0.f;
        if (gi < n) {
            u0 = o_u0[gi]; u1 = o_u1[gi];
            float rc2 = o_rc2[gi];
            float ddx = fmaxf(fmaxf(x0 - u0, u0 - x1), 0.0f);
            float ddy = fmaxf(fmaxf(y0 - u1, u1 - y1), 0.0f);
            keep = (ddx*ddx + ddy*ddy) <= rc2;
        }
        unsigned m = __ballot_sync(0xffffffffu, keep);
        if (lane == 0) wc[warp] = __popc(m);
        __syncthreads();
        int cnt = wc[0] + wc[1];
        if (keep) {
            int slot = (warp ? wc[0] : 0) + __popc(m & ((1u << lane) - 1u));
            su0[slot]=u0; su1[slot]=u1;
            sA[slot]=o_hA[gi]; sB[slot]=o_hB[gi]; sC[slot]=o_hC[gi];
            sal[slot]=o_al[gi]; scr[slot]=o_cr[gi]; scg[slot]=o_cg[gi]; scb[slot]=o_cb[gi];
        }
        __syncthreads();

        if (tau > 1e-4f) {
            for (int s = 0; s < cnt; s++) {
                float ddx = su0[s] - fpx, ddy = su1[s] - fpy;
                float p = sA[s]*ddx*ddx + sC[s]*ddy*ddy + sB[s]*ddx*ddy;
                p = fminf(p, 0.0f);
                float ap = fminf(sal[s] * expf(p), 0.99f);
                if (ap < (1.0f/255.0f)) ap = 0.0f;
                float wgt = (tau > 1e-4f) ? ap * tau : 0.0f;
                acc0 += scr[s] * wgt;
                acc1 += scg[s] * wgt;
                acc2 += scb[s] * wgt;
                tau *= (1.0f - ap);
            }
        }
        if (__syncthreads_and(tau <= 1e-4f)) break;
    }

    int pix = (blockIdx.y * 8 + tyr) * 96 + blockIdx.x * 8 + txr;
    out[pix]            = acc0;
    out[NPIX + pix]     = acc1;
    out[2*NPIX + pix]   = acc2;
}

extern "C" void kernel_launch(void* const* d_in, const int* in_sizes, int n_in,
                              void* d_out, int out_size)
{
    const float* pws   = (const float*)d_in[0];
    const float* lows  = (const float*)d_in[1];
    const float* highs = (const float*)d_in[2];
    const float* araw  = (const float*)d_in[3];
    const float* sraw  = (const float*)d_in[4];
    const float* qraw  = (const float*)d_in[5];
    // d_in[6] = us (unused)
    const float* Rcw   = (const float*)d_in[7];
    const float* tcw   = (const float*)d_in[8];
    const float* cam   = (const float*)d_in[9];
    float* out = (float*)d_out;

    int n = in_sizes[0] / 3;
    if (n > NMAX) n = NMAX;

    float* out_areas = out + 3 * NPIX;

    prep_kernel<<<(n + 255) / 256, 256>>>(pws, lows, highs, araw, sraw, qraw,
                                          Rcw, tcw, cam, out_areas, n);
    sort_kernel<<<1, 1024>>>(n);
    dim3 grid(12, 12), blk(8, 8);
    blend_kernel<<<grid, blk>>>(out, n);
}

// round 2
// speedup vs baseline: 1.6258x; 1.6258x over previous
#include <cuda_runtime.h>
#include <math.h>

#define NMAX 4096
#define NPIX (96*96)
#define PB 128   // prep block

// ---- packed scratch (device globals) ----
__device__ float4 g_p0[NMAX];   // u0, u1, rc2, hA
__device__ float4 g_p1[NMAX];   // hB, hC, alpha, cr
__device__ float2 g_p2[NMAX];   // cg, cb
__device__ unsigned long long g_key[NMAX];
// depth-sorted
__device__ float4 o_p0[NMAX];
__device__ float4 o_p1[NMAX];
__device__ float2 o_p2[NMAX];

// ---------------- Kernel A: per-gaussian preprocess (smem-staged) ----------------
__global__ void prep_kernel(const float* __restrict__ pws,
                            const float* __restrict__ lows,
                            const float* __restrict__ highs,
                            const float* __restrict__ araw,
                            const float* __restrict__ sraw,
                            const float* __restrict__ qraw,
                            const float* __restrict__ Rcw,
                            const float* __restrict__ tcw,
                            const float* __restrict__ cam,
                            float* __restrict__ out_areas,
                            int n)
{
    __shared__ float s_high[PB*45];
    __shared__ float s_low[PB*3], s_pw[PB*3], s_sr[PB*3], s_q[PB*4], s_a[PB];

    int base = blockIdx.x * PB;
    int tid  = threadIdx.x;

    for (int k = tid; k < PB*45 && base*45 + k < n*45; k += PB) s_high[k] = highs[base*45 + k];
    for (int k = tid; k < PB*3  && base*3  + k < n*3;  k += PB) {
        s_low[k] = lows[base*3+k]; s_pw[k] = pws[base*3+k]; s_sr[k] = sraw[base*3+k];
    }
    for (int k = tid; k < PB*4 && base*4 + k < n*4; k += PB) s_q[k] = qraw[base*4+k];
    if (tid < PB && base + tid < n) s_a[tid] = araw[base + tid];
    __syncthreads();

    int i = base + tid;
    if (i >= n) return;

    float fx = cam[0], fy = cam[1], cx = cam[2], cy = cam[3];
    float R00=Rcw[0],R01=Rcw[1],R02=Rcw[2];
    float R10=Rcw[3],R11=Rcw[4],R12=Rcw[5];
    float R20=Rcw[6],R21=Rcw[7],R22=Rcw[8];
    float t0=tcw[0],t1=tcw[1],t2=tcw[2];

    float pwx=s_pw[3*tid], pwy=s_pw[3*tid+1], pwz=s_pw[3*tid+2];
    float pcx = R00*pwx + R01*pwy + R02*pwz + t0;
    float pcy = R10*pwx + R11*pwy + R12*pwz + t1;
    float pcz = R20*pwx + R21*pwy + R22*pwz + t2;
    float depth = pcz;
    float zs = (depth > 1e-6f) ? depth : 1e-6f;
    float inv_z = 1.0f / zs;
    float u0 = fx * pcx * inv_z + cx;
    float u1 = fy * pcy * inv_z + cy;

    float s0 = expf(s_sr[3*tid]), s1 = expf(s_sr[3*tid+1]), s2 = expf(s_sr[3*tid+2]);
    float qw=s_q[4*tid], qx=s_q[4*tid+1], qy=s_q[4*tid+2], qz=s_q[4*tid+3];
    float qn = rsqrtf(qw*qw + qx*qx + qy*qy + qz*qz);
    qw*=qn; qx*=qn; qy*=qn; qz*=qn;
    float r00 = 1.f-2.f*(qy*qy+qz*qz), r01 = 2.f*(qx*qy-qw*qz), r02 = 2.f*(qx*qz+qw*qy);
    float r10 = 2.f*(qx*qy+qw*qz), r11 = 1.f-2.f*(qx*qx+qz*qz), r12 = 2.f*(qy*qz-qw*qx);
    float r20 = 2.f*(qx*qz-qw*qy), r21 = 2.f*(qy*qz+qw*qx), r22 = 1.f-2.f*(qx*qx+qy*qy);

    float v0=s0*s0, v1=s1*s1, v2=s2*s2;
    float c00 = v0*r00*r00 + v1*r01*r01 + v2*r02*r02;
    float c01 = v0*r00*r10 + v1*r01*r11 + v2*r02*r12;
    float c02 = v0*r00*r20 + v1*r01*r21 + v2*r02*r22;
    float c11 = v0*r10*r10 + v1*r11*r11 + v2*r12*r12;
    float c12 = v0*r10*r20 + v1*r11*r21 + v2*r12*r22;
    float c22 = v0*r20*r20 + v1*r21*r21 + v2*r22*r22;

    float limx = 1.3f * (96.0f / (2.0f*fx));
    float limy = 1.3f * (96.0f / (2.0f*fy));
    float txc = fminf(fmaxf(pcx*inv_z, -limx), limx) * zs;
    float tyc = fminf(fmaxf(pcy*inv_z, -limy), limy) * zs;
    float J00 = fx*inv_z, J02 = -fx*txc*inv_z*inv_z;
    float J11 = fy*inv_z, J12 = -fy*tyc*inv_z*inv_z;

    float T00 = J00*R00 + J02*R20, T01 = J00*R01 + J02*R21, T02 = J00*R02 + J02*R22;
    float T10 = J11*R10 + J12*R20, T11 = J11*R11 + J12*R21, T12 = J11*R12 + J12*R22;

    float m00 = T00*c00 + T01*c01 + T02*c02;
    float m01 = T00*c01 + T01*c11 + T02*c12;
    float m02 = T00*c02 + T01*c12 + T02*c22;
    float m10 = T10*c00 + T11*c01 + T12*c02;
    float m11 = T10*c01 + T11*c11 + T12*c12;
    float m12 = T10*c02 + T11*c12 + T12*c22;

    float A  = m00*T00 + m01*T01 + m02*T02 + 0.3f;
    float Bb = m00*T10 + m01*T11 + m02*T12;
    float Cc = m10*T10 + m11*T11 + m12*T12 + 0.3f;

    float det  = A*Cc - Bb*Bb;
    float idet = 1.0f / det;
    float hA = -0.5f * Cc * idet;
    float hC = -0.5f * A  * idet;
    float hB =  Bb * idet;

    float mid = 0.5f * (A + Cc);
    float lam = mid + sqrtf(fmaxf(mid*mid - det, 0.1f));
    float radius = ceilf(3.0f * sqrtf(lam));
    out_areas[2*i]   = radius;
    out_areas[2*i+1] = radius;

    float alpha = 1.0f / (1.0f + expf(-s_a[tid]));
    if (!(depth > 0.2f)) alpha = 0.0f;

    float rc2;
    if (alpha * 255.0f <= 1.0f) {
        rc2 = -1.0f;
    } else {
        float theta = 2.0f * logf(255.0f * alpha);
        rc2 = lam * theta * 1.002f + 1e-2f;
    }

    // SH color
    float wx = R00*t0 + R10*t1 + R20*t2;
    float wy = R01*t0 + R11*t1 + R21*t2;
    float wz = R02*t0 + R12*t1 + R22*t2;
    float dx0 = pwx + wx, dy0 = pwy + wy, dz0 = pwz + wz;
    float dn = rsqrtf(dx0*dx0 + dy0*dy0 + dz0*dz0);
    float x = dx0*dn, y = dy0*dn, z = dz0*dn;
    float xx=x*x, yy=y*y, zz=z*z, xy=x*y, yz=y*z, xz=x*z;

    float b1 = -0.4886025119029199f*y, b2 = 0.4886025119029199f*z, b3 = -0.4886025119029199f*x;
    float b4 =  1.0925484305920792f  * xy;
    float b5 = -1.0925484305920792f  * yz;
    float b6 =  0.31539156525252005f * (2.f*zz - xx - yy);
    float b7 = -1.0925484305920792f  * xz;
    float b8 =  0.5462742152960396f  * (xx - yy);
    float b9  = -0.5900435899266435f * y * (3.f*xx - yy);
    float b10 =  2.890611442640554f  * xy * z;
    float b11 = -0.4570457994644658f * y * (4.f*zz - xx - yy);
    float b12 =  0.3731763325901154f * z * (2.f*zz - 3.f*xx - 3.f*yy);
    float b13 = -0.4570457994644658f * x * (4.f*zz - xx - yy);
    float b14 =  1.445305721320277f  * z * (xx - yy);
    float b15 = -0.5900435899266435f * x * (xx - 3.f*yy);

    const float* hs = s_high + 45*tid;
    float col[3];
    #pragma unroll
    for (int ch = 0; ch < 3; ch++) {
        float c = 0.28209479177387814f * s_low[3*tid + ch];
        c += b1  * hs[0*3+ch]  + b2  * hs[1*3+ch]  + b3  * hs[2*3+ch];
        c += b4  * hs[3*3+ch]  + b5  * hs[4*3+ch]  + b6  * hs[5*3+ch];
        c += b7  * hs[6*3+ch]  + b8  * hs[7*3+ch];
        c += b9  * hs[8*3+ch]  + b10 * hs[9*3+ch]  + b11 * hs[10*3+ch];
        c += b12 * hs[11*3+ch] + b13 * hs[12*3+ch] + b14 * hs[13*3+ch];
        c += b15 * hs[14*3+ch];
        col[ch] = fmaxf(c + 0.5f, 0.0f);
    }

    g_p0[i] = make_float4(u0, u1, rc2, hA);
    g_p1[i] = make_float4(hB, hC, alpha, col[0]);
    g_p2[i] = make_float2(col[1], col[2]);

    // sortable 64-bit key: (monotone float bits << 32) | index  -> exact stable argsort
    unsigned int b = __float_as_uint(depth);
    b = (b & 0x80000000u) ? ~b : (b | 0x80000000u);
    g_key[i] = ((unsigned long long)b << 32) | (unsigned int)i;
}

// ---------------- Kernel B: rank-by-counting sort (exact stable argsort) ----------------
// grid = n/32 blocks, 256 threads. 8-way split of the j loop per gaussian.
__global__ void rank_kernel(int n)
{
    __shared__ unsigned long long sk[NMAX];
    int tid = threadIdx.x;
    for (int k = tid; k < n; k += 256) sk[k] = g_key[k];
    __syncthreads();

    int il = tid >> 3;          // 0..31 local gaussian
    int sp = tid & 7;           // split 0..7
    int i  = blockIdx.x * 32 + il;
    if (i >= n) return;
    unsigned long long ki = sk[i];

    int r = 0;
    #pragma unroll 8
    for (int j = sp; j < n; j += 8) r += (sk[j] < ki) ? 1 : 0;

    r += __shfl_down_sync(0xffffffffu, r, 4, 8);
    r += __shfl_down_sync(0xffffffffu, r, 2, 8);
    r += __shfl_down_sync(0xffffffffu, r, 1, 8);

    if (sp == 0) {
        o_p0[r] = g_p0[i];
        o_p1[r] = g_p1[i];
        o_p2[r] = g_p2[i];
    }
}

// ---------------- Kernel C: tiled alpha blending ----------------
// grid (12,12) tiles of 8x8 pixels; 256 threads; 256-gaussian chunks.
__global__ void blend_kernel(float* __restrict__ out, int n)
{
    __shared__ float4 sm0[256];   // u0,u1,hA,hB
    __shared__ float4 sm1[256];   // hC,al,cr,cg
    __shared__ float  sm2[256];   // cb
    __shared__ int wcnt[8];

    int tid = threadIdx.x;
    int warp = tid >> 5, lane = tid & 31;
    int px = tid & 7, py = (tid >> 3) & 7;
    float fpx = (float)(blockIdx.x * 8 + px);
    float fpy = (float)(blockIdx.y * 8 + py);
    float x0 = (float)(blockIdx.x * 8), x1 = x0 + 7.0f;
    float y0 = (float)(blockIdx.y * 8), y1 = y0 + 7.0f;

    float tau = (tid < 64) ? 1.0f : 0.0f;
    float a0 = 0.f, a1 = 0.f, a2 = 0.f;

    for (int base = 0; base < n; base += 256) {
        int gi = base + tid;
        bool keep = false;
        float4 p0 = make_float4(0.f,0.f,0.f,0.f);
        if (gi < n) {
            p0 = o_p0[gi];
            float ddx = fmaxf(fmaxf(x0 - p0.x, p0.x - x1), 0.0f);
            float ddy = fmaxf(fmaxf(y0 - p0.y, p0.y - y1), 0.0f);
            keep = (ddx*ddx + ddy*ddy) <= p0.z;
        }
        unsigned m = __ballot_sync(0xffffffffu, keep);
        if (lane == 0) wcnt[warp] = __popc(m);
        __syncthreads();
        int off = 0, cnt = 0;
        #pragma unroll
        for (int w = 0; w < 8; w++) { int c = wcnt[w]; if (w < warp) off += c; cnt += c; }
        if (keep) {
            int slot = off + __popc(m & ((1u << lane) - 1u));
            float4 p1 = o_p1[gi];
            float2 p2 = o_p2[gi];
            sm0[slot] = make_float4(p0.x, p0.y, p0.w, p1.x);
            sm1[slot] = make_float4(p1.y, p1.z, p1.w, p2.x);
            sm2[slot] = p2.y;
        }
        __syncthreads();

        if (tau > 1e-4f) {
            for (int s = 0; s < cnt; s++) {
                float4 q0 = sm0[s];
                float ddx = q0.x - fpx, ddy = q0.y - fpy;
                float4 q1 = sm1[s];
                float p = q0.z*ddx*ddx + q1.x*ddy*ddy + q0.w*ddx*ddy;
                p = fminf(p, 0.0f);
                float ap = fminf(q1.y * __expf(p), 0.99f);
                if (ap >= (1.0f/255.0f)) {
                    float w = ap * tau;
                    a0 += q1.z * w;
                    a1 += q1.w * w;
                    a2 += sm2[s] * w;
                    tau *= (1.0f - ap);
                    if (tau <= 1e-4f) break;   // all later wgt are exactly 0 in the reference
                }
            }
        }
        if (__syncthreads_and(tau <= 1e-4f)) break;
    }

    if (tid < 64) {
        int pix = (blockIdx.y * 8 + py) * 96 + blockIdx.x * 8 + px;
        out[pix]          = a0;
        out[NPIX + pix]   = a1;
        out[2*NPIX + pix] = a2;
    }
}

extern "C" void kernel_launch(void* const* d_in, const int* in_sizes, int n_in,
                              void* d_out, int out_size)
{
    const float* pws   = (const float*)d_in[0];
    const float* lows  = (const float*)d_in[1];
    const float* highs = (const float*)d_in[2];
    const float* araw  = (const float*)d_in[3];
    const float* sraw  = (const float*)d_in[4];
    const float* qraw  = (const float*)d_in[5];
    const float* Rcw   = (const float*)d_in[7];
    const float* tcw   = (const float*)d_in[8];
    const float* cam   = (const float*)d_in[9];
    float* out = (float*)d_out;

    int n = in_sizes[0] / 3;
    if (n > NMAX) n = NMAX;

    float* out_areas = out + 3 * NPIX;

    prep_kernel<<<(n + PB - 1) / PB, PB>>>(pws, lows, highs, araw, sraw, qraw,
                                           Rcw, tcw, cam, out_areas, n);
    rank_kernel<<<(n + 31) / 32, 256>>>(n);
    dim3 grid(12, 12), blk(256, 1);
    blend_kernel<<<grid, blk>>>(out, n);
}